// round 1
// baseline (speedup 1.0000x reference)
#include <cuda_runtime.h>
#include <math.h>

#define SDIM 32768   // 32*32*32 spatial
#define HDIM 32

// -------- scratch (static device globals; no runtime allocation) --------
__device__ float g_qkv[384 * SDIM];     // 48 MB
__device__ float g_sam[128 * SDIM];     // 16 MB
__device__ float g_y1 [128 * SDIM];     // 16 MB (proj output, pre-norm)
__device__ float g_hid[512 * SDIM];     // 64 MB
__device__ float g_t2 [128 * SDIM];     // 16 MB
__device__ float g_stats[512];          // m1[128] r1[128] m2[128] r2[128]

// ============================================================
// Generic tiled SGEMM: Y[M,S] = W[M,K] * X[K,S]  (S = 32768)
//   WT:    W is stored transposed, i.e. element (m,k) at W[k*M + m]
//   RELU:  relu epilogue
//   NORMX: X row k is normalized on load: (x - mx[k]) * rx[k]
//   RESID: add normalized residual: (resid[m,s] - mr[m]) * rr[m]
// Tile: 64(M) x 64(S) x 32(K), 256 threads, 4x4 per thread.
// All dims divide the tiles exactly for this problem.
// ============================================================
template<bool WT, bool RELU, bool NORMX, bool RESID>
__global__ void __launch_bounds__(256)
gemm64(const float* __restrict__ W, const float* __restrict__ X,
       float* __restrict__ Y, const float* __restrict__ bias,
       int M, int Kd,
       const float* __restrict__ mx, const float* __restrict__ rx,
       const float* __restrict__ resid,
       const float* __restrict__ mr, const float* __restrict__ rr)
{
    const int S = SDIM;
    __shared__ __align__(16) float sW[32][68];
    __shared__ __align__(16) float sX[32][68];

    const int bm = blockIdx.y * 64;
    const int bn = blockIdx.x * 64;
    const int tid = threadIdx.x;
    const int tx = tid & 15;        // S direction (16)
    const int ty = tid >> 4;        // M direction (16)

    float acc[4][4];
#pragma unroll
    for (int i = 0; i < 4; i++)
#pragma unroll
        for (int j = 0; j < 4; j++) acc[i][j] = 0.f;

    for (int k0 = 0; k0 < Kd; k0 += 32) {
        // ---- load W tile (64x32) ----
#pragma unroll
        for (int j = 0; j < 8; j++) {
            int l = tid + j * 256;
            if (WT) {
                int m = l & 63, kk = l >> 6;
                sW[kk][m] = W[(k0 + kk) * M + bm + m];
            } else {
                int kk = l & 31, m = l >> 5;
                sW[kk][m] = W[(bm + m) * Kd + k0 + kk];
            }
        }
        // ---- load X tile (32x64), optionally normalized ----
#pragma unroll
        for (int j = 0; j < 8; j++) {
            int l = tid + j * 256;
            int n = l & 63, kk = l >> 6;
            float v = X[(size_t)(k0 + kk) * S + bn + n];
            if (NORMX) v = (v - mx[k0 + kk]) * rx[k0 + kk];
            sX[kk][n] = v;
        }
        __syncthreads();

#pragma unroll
        for (int kk = 0; kk < 32; kk++) {
            float4 a = *reinterpret_cast<const float4*>(&sW[kk][ty << 2]);
            float4 b = *reinterpret_cast<const float4*>(&sX[kk][tx << 2]);
            float av[4] = {a.x, a.y, a.z, a.w};
            float bv[4] = {b.x, b.y, b.z, b.w};
#pragma unroll
            for (int i = 0; i < 4; i++)
#pragma unroll
                for (int j = 0; j < 4; j++)
                    acc[i][j] += av[i] * bv[j];
        }
        __syncthreads();
    }

    // ---- epilogue ----
#pragma unroll
    for (int i = 0; i < 4; i++) {
        int m = bm + (ty << 2) + i;
        float bv = bias[m];
        float mrv = 0.f, rrv = 0.f;
        if (RESID) { mrv = mr[m]; rrv = rr[m]; }
#pragma unroll
        for (int j = 0; j < 4; j++) {
            int n = bn + (tx << 2) + j;
            float v = acc[i][j] + bv;
            if (RELU)  v = fmaxf(v, 0.f);
            if (RESID) v += (resid[(size_t)m * S + n] - mrv) * rrv;
            Y[(size_t)m * S + n] = v;
        }
    }
}

// ============================================================
// Neighborhood attention: K=3 window (clamped, NAT-style), G=8, D=16
// grid (W/4, H, G), block (32, 4): lane = z, ty = w-subtile
// ============================================================
__global__ void __launch_bounds__(128)
attn_kernel(const float* __restrict__ qkv, float* __restrict__ sam,
            const float* __restrict__ rpb)
{
    const int S = SDIM;
    const int g = blockIdx.z;
    const int h = blockIdx.y;
    const int w = blockIdx.x * 4 + threadIdx.y;
    const int z = threadIdx.x;

    __shared__ float srpb[125];
    int tid = threadIdx.y * 32 + threadIdx.x;
    if (tid < 125) srpb[tid] = rpb[g * 125 + tid];
    __syncthreads();

    const int s = (h * HDIM + w) * HDIM + z;

    float qv[16];
    const float* qp = qkv + (size_t)(g * 16) * S + s;
#pragma unroll
    for (int d = 0; d < 16; d++) qv[d] = qp[(size_t)d * S];

    const int sh = min(max(h - 1, 0), HDIM - 3);
    const int sw = min(max(w - 1, 0), HDIM - 3);
    const int sz = min(max(z - 1, 0), HDIM - 3);

    float logits[27];
    const float* kp = qkv + (size_t)(128 + g * 16) * S;
#pragma unroll
    for (int jh = 0; jh < 3; jh++)
#pragma unroll
    for (int jw = 0; jw < 3; jw++)
#pragma unroll
    for (int jz = 0; jz < 3; jz++) {
        int ns = ((sh + jh) * HDIM + (sw + jw)) * HDIM + (sz + jz);
        float dot = 0.f;
#pragma unroll
        for (int d = 0; d < 16; d++) dot += qv[d] * kp[(size_t)d * S + ns];
        int rh = sh + jh - h + 2;
        int rw = sw + jw - w + 2;
        int rz = sz + jz - z + 2;
        logits[jh * 9 + jw * 3 + jz] = dot * 0.25f + srpb[(rh * 5 + rw) * 5 + rz];
    }

    float mx = logits[0];
#pragma unroll
    for (int j = 1; j < 27; j++) mx = fmaxf(mx, logits[j]);
    float sum = 0.f;
#pragma unroll
    for (int j = 0; j < 27; j++) { logits[j] = __expf(logits[j] - mx); sum += logits[j]; }
    float inv = 1.f / sum;

    float accv[16];
#pragma unroll
    for (int d = 0; d < 16; d++) accv[d] = 0.f;

    const float* vp = qkv + (size_t)(256 + g * 16) * S;
#pragma unroll
    for (int jh = 0; jh < 3; jh++)
#pragma unroll
    for (int jw = 0; jw < 3; jw++)
#pragma unroll
    for (int jz = 0; jz < 3; jz++) {
        int ns = ((sh + jh) * HDIM + (sw + jw)) * HDIM + (sz + jz);
        float p = logits[jh * 9 + jw * 3 + jz] * inv;
#pragma unroll
        for (int d = 0; d < 16; d++) accv[d] += p * vp[(size_t)d * S + ns];
    }

    float* op = sam + (size_t)(g * 16) * S + s;
#pragma unroll
    for (int d = 0; d < 16; d++) op[(size_t)d * S] = accv[d];
}

// ============================================================
// Per-channel instance-norm statistics over S=32768
// ============================================================
__global__ void __launch_bounds__(256)
inorm_stats(const float* __restrict__ Y, float* __restrict__ mean,
            float* __restrict__ rstd)
{
    const int c = blockIdx.x;
    const float* p = Y + (size_t)c * SDIM;
    float s = 0.f, s2 = 0.f;
    for (int i = threadIdx.x; i < SDIM; i += 256) {
        float v = p[i];
        s += v; s2 += v * v;
    }
    __shared__ float sh1[256], sh2[256];
    int t = threadIdx.x;
    sh1[t] = s; sh2[t] = s2;
    __syncthreads();
    for (int o = 128; o > 0; o >>= 1) {
        if (t < o) { sh1[t] += sh1[t + o]; sh2[t] += sh2[t + o]; }
        __syncthreads();
    }
    if (t == 0) {
        float m = sh1[0] * (1.f / SDIM);
        float var = sh2[0] * (1.f / SDIM) - m * m;
        mean[c] = m;
        rstd[c] = rsqrtf(var + 1e-5f);
    }
}

// skip = inorm(t2) + x
__global__ void __launch_bounds__(256)
finalize_skip(const float* __restrict__ t2, const float* __restrict__ x,
              const float* __restrict__ m2, const float* __restrict__ r2,
              float* __restrict__ skip)
{
    int idx = blockIdx.x * 256 + threadIdx.x;   // 128*32768 total
    int c = idx >> 15;
    skip[idx] = (t2[idx] - m2[c]) * r2[c] + x[idx];
}

// down = maxpool2x2x2(skip)
__global__ void __launch_bounds__(256)
maxpool_kernel(const float* __restrict__ skip, float* __restrict__ down)
{
    int idx = blockIdx.x * 256 + threadIdx.x;   // 128*16*16*16 total
    int oz = idx & 15;
    int ow = (idx >> 4) & 15;
    int oh = (idx >> 8) & 15;
    int c  = idx >> 12;
    const float* p = skip + (((size_t)c * HDIM + oh * 2) * HDIM + ow * 2) * HDIM + oz * 2;
    float m = p[0];
    m = fmaxf(m, p[1]);
    m = fmaxf(m, p[HDIM]);     m = fmaxf(m, p[HDIM + 1]);
    m = fmaxf(m, p[HDIM*HDIM]);     m = fmaxf(m, p[HDIM*HDIM + 1]);
    m = fmaxf(m, p[HDIM*HDIM + HDIM]); m = fmaxf(m, p[HDIM*HDIM + HDIM + 1]);
    down[idx] = m;
}

// ============================================================
extern "C" void kernel_launch(void* const* d_in, const int* in_sizes, int n_in,
                              void* d_out, int out_size)
{
    const float* x      = (const float*)d_in[0];
    const float* qkv_w  = (const float*)d_in[1];
    const float* qkv_b  = (const float*)d_in[2];
    const float* proj_w = (const float*)d_in[3];
    const float* proj_b = (const float*)d_in[4];
    const float* rpb    = (const float*)d_in[5];
    const float* w1     = (const float*)d_in[6];
    const float* b1     = (const float*)d_in[7];
    const float* w2     = (const float*)d_in[8];
    const float* b2     = (const float*)d_in[9];

    float *qkv, *sam, *y1, *hid, *t2, *st;
    cudaGetSymbolAddress((void**)&qkv, g_qkv);
    cudaGetSymbolAddress((void**)&sam, g_sam);
    cudaGetSymbolAddress((void**)&y1,  g_y1);
    cudaGetSymbolAddress((void**)&hid, g_hid);
    cudaGetSymbolAddress((void**)&t2,  g_t2);
    cudaGetSymbolAddress((void**)&st,  g_stats);
    float* m1 = st, *r1 = st + 128, *m2 = st + 256, *r2 = st + 384;

    const int SB = SDIM / 64;   // 512 S-blocks

    // 1) QKV projection: (384,128) x (128,S)
    gemm64<false,false,false,false><<<dim3(SB, 6), 256>>>(
        qkv_w, x, qkv, qkv_b, 384, 128, nullptr, nullptr, nullptr, nullptr, nullptr);

    // 2) Neighborhood attention
    attn_kernel<<<dim3(8, 32, 8), dim3(32, 4)>>>(qkv, sam, rpb);

    // 3) Output projection: (128,128) x (128,S)
    gemm64<false,false,false,false><<<dim3(SB, 2), 256>>>(
        proj_w, sam, y1, proj_b, 128, 128, nullptr, nullptr, nullptr, nullptr, nullptr);

    // 4) Instance-norm stats of y1
    inorm_stats<<<128, 256>>>(y1, m1, r1);

    // 5) MLP fc1 + relu, with inorm applied to X on load:
    //    hid[f,s] = relu( sum_c w1[c,f] * xn[c,s] + b1[f] )
    gemm64<true,true,true,false><<<dim3(SB, 8), 256>>>(
        w1, y1, hid, b1, 512, 128, m1, r1, nullptr, nullptr, nullptr);

    // 6) MLP fc2 + normalized residual:
    //    t2[c,s] = sum_f w2[f,c]*hid[f,s] + b2[c] + xn[c,s]
    gemm64<true,false,false,true><<<dim3(SB, 2), 256>>>(
        w2, hid, t2, b2, 128, 512, nullptr, nullptr, y1, m1, r1);

    // 7) Instance-norm stats of t2
    inorm_stats<<<128, 256>>>(t2, m2, r2);

    // 8) skip = inorm(t2) + x   (output layout: [down | skip])
    float* out  = (float*)d_out;
    float* down = out;                   // 128*16*16*16 = 524288
    float* skip = out + 524288;          // 128*32*32*32 = 4194304
    finalize_skip<<<(128 * SDIM) / 256, 256>>>(t2, x, m2, r2, skip);

    // 9) down = maxpool(skip)
    maxpool_kernel<<<524288 / 256, 256>>>(skip, down);
}

// round 3
// speedup vs baseline: 1.2695x; 1.2695x over previous
#include <cuda_runtime.h>
#include <stdint.h>
#include <math.h>

#define S_TOT 32768
#define HD 32

// ---------------- scratch (static device globals) ----------------
__device__ float g_xt  [S_TOT * 128];   // x transposed [S,C]; later reused as y1n
__device__ float g_qkv [S_TOT * 384];   // [S, 384]
__device__ float g_sam [S_TOT * 128];
__device__ float g_y1  [S_TOT * 128];
__device__ float g_hid [S_TOT * 512];
__device__ float g_t2  [S_TOT * 128];
__device__ float g_w1t [512 * 128];
__device__ float g_w2t [128 * 512];
__device__ float g_part[2 * S_TOT];
__device__ float g_stats[512];          // m1,r1,m2,r2

// ---------------- helpers ----------------
__device__ __forceinline__ uint32_t smem_u32(const void* p) {
    uint32_t a;
    asm("{ .reg .u64 t; cvta.to.shared.u64 t, %1; cvt.u32.u64 %0, t; }"
        : "=r"(a) : "l"(p));
    return a;
}
__device__ __forceinline__ void cp16(uint32_t s, const void* g) {
    asm volatile("cp.async.cg.shared.global [%0], [%1], 16;" :: "r"(s), "l"(g));
}
__device__ __forceinline__ void cp_commit() {
    asm volatile("cp.async.commit_group;" ::: "memory");
}
template<int N>
__device__ __forceinline__ void cp_wait() {
    asm volatile("cp.async.wait_group %0;" :: "n"(N) : "memory");
}
__device__ __forceinline__ uint32_t f2tf32(float f) {
    uint32_t u;
    asm("cvt.rna.tf32.f32 %0, %1;" : "=r"(u) : "f"(f));
    return u;
}

// ============================================================
// tf32 mma.sync GEMM: Y[s0..s0+128, n0..n0+128) = A[S,Kd] * B[N,Kd]^T
// CTA 128x128, 8 warps (2 M x 4 N), warp tile 64x32, K-chunk 32,
// cp.async double buffer. smem row stride 36 floats (conflict-free frags).
// ============================================================
#define KSTR 36
#define TILE_F (128 * KSTR)           // floats per tile buffer

template<bool RELU, bool RESID>
__global__ void __launch_bounds__(256)
gemm_mma(const float* __restrict__ A, const float* __restrict__ B,
         float* __restrict__ Y, const float* __restrict__ bias,
         int Kd, int Nout, const float* __restrict__ resid)
{
    extern __shared__ float dsm[];
    float* sA[2] = { dsm,            dsm + 2 * TILE_F };
    float* sB[2] = { dsm + TILE_F,   dsm + 3 * TILE_F };

    const int tid = threadIdx.x;
    const int wid = tid >> 5;
    const int lane = tid & 31;
    const int wm = wid & 1;          // M-dir warp (2)
    const int wn = wid >> 1;         // N-dir warp (4)
    const int rq = lane >> 2;
    const int cq = lane & 3;
    const int s0 = blockIdx.x * 128;
    const int n0 = blockIdx.y * 128;

    const int nch = Kd >> 5;

    float acc[4][4][4];
#pragma unroll
    for (int mi = 0; mi < 4; mi++)
#pragma unroll
        for (int ni = 0; ni < 4; ni++)
#pragma unroll
            for (int r = 0; r < 4; r++) acc[mi][ni][r] = 0.f;

    // ---- async tile loader: chunk ci -> buffer buf ----
    auto load_chunk = [&](int ci, int buf) {
        const int kc = ci << 5;
        uint32_t aBase = smem_u32(sA[buf]);
        uint32_t bBase = smem_u32(sB[buf]);
#pragma unroll
        for (int j = 0; j < 4; j++) {
            int idx = tid + j * 256;          // 0..1023
            int row = idx >> 3, seg = idx & 7;
            cp16(aBase + (row * KSTR + seg * 4) * 4,
                 &A[(size_t)(s0 + row) * Kd + kc + seg * 4]);
            cp16(bBase + (row * KSTR + seg * 4) * 4,
                 &B[(size_t)(n0 + row) * Kd + kc + seg * 4]);
        }
        cp_commit();
    };

    load_chunk(0, 0);

    for (int ci = 0; ci < nch; ci++) {
        if (ci + 1 < nch) { load_chunk(ci + 1, (ci + 1) & 1); cp_wait<1>(); }
        else              { cp_wait<0>(); }
        __syncthreads();

        const float* pA = sA[ci & 1] + wm * 64 * KSTR;
        const float* pB = sB[ci & 1] + wn * 32 * KSTR;

#pragma unroll
        for (int ks = 0; ks < 4; ks++) {
            const int kof = ks * 8 + cq;
            uint32_t a[4][4], b[4][2];
#pragma unroll
            for (int mi = 0; mi < 4; mi++) {
                const float* p = pA + (mi * 16 + rq) * KSTR + kof;
                a[mi][0] = f2tf32(p[0]);
                a[mi][1] = f2tf32(p[8 * KSTR]);
                a[mi][2] = f2tf32(p[4]);
                a[mi][3] = f2tf32(p[8 * KSTR + 4]);
            }
#pragma unroll
            for (int ni = 0; ni < 4; ni++) {
                const float* p = pB + (ni * 8 + rq) * KSTR + kof;
                b[ni][0] = f2tf32(p[0]);
                b[ni][1] = f2tf32(p[4]);
            }
#pragma unroll
            for (int mi = 0; mi < 4; mi++)
#pragma unroll
                for (int ni = 0; ni < 4; ni++) {
                    asm volatile(
                        "mma.sync.aligned.m16n8k8.row.col.f32.tf32.tf32.f32 "
                        "{%0,%1,%2,%3}, {%4,%5,%6,%7}, {%8,%9}, {%0,%1,%2,%3};"
                        : "+f"(acc[mi][ni][0]), "+f"(acc[mi][ni][1]),
                          "+f"(acc[mi][ni][2]), "+f"(acc[mi][ni][3])
                        : "r"(a[mi][0]), "r"(a[mi][1]), "r"(a[mi][2]), "r"(a[mi][3]),
                          "r"(b[ni][0]), "r"(b[ni][1]));
                }
        }
        __syncthreads();
    }

    // ---- epilogue ----
#pragma unroll
    for (int ni = 0; ni < 4; ni++) {
        const int col = n0 + wn * 32 + ni * 8 + cq * 2;
        const float b0 = bias[col], b1 = bias[col + 1];
#pragma unroll
        for (int mi = 0; mi < 4; mi++) {
            const int row0 = s0 + wm * 64 + mi * 16 + rq;
#pragma unroll
            for (int half = 0; half < 2; half++) {
                const int row = row0 + half * 8;
                float v0 = acc[mi][ni][half * 2 + 0] + b0;
                float v1 = acc[mi][ni][half * 2 + 1] + b1;
                if (RELU) { v0 = fmaxf(v0, 0.f); v1 = fmaxf(v1, 0.f); }
                if (RESID) {
                    const float* rp = resid + (size_t)row * 128 + col;
                    v0 += rp[0]; v1 += rp[1];
                }
                float2 o; o.x = v0; o.y = v1;
                *(float2*)&Y[(size_t)row * Nout + col] = o;
            }
        }
    }
}

// ============================================================
// Neighborhood attention in [S,C] layout. block=(32z x 8g)=256, grid=(w,h)
// ============================================================
__global__ void __launch_bounds__(256)
attn2(const float* __restrict__ qkv, float* __restrict__ sam,
      const float* __restrict__ rpb)
{
    __shared__ float slab[32][132];
    __shared__ float srpb[8][125];
    const int h = blockIdx.y, w = blockIdx.x;
    const int tid = threadIdx.x;
    const int z = tid >> 3, g = tid & 7;

    for (int i = tid; i < 1000; i += 256) srpb[i / 125][i % 125] = rpb[i];

    const int s = (h * HD + w) * HD + z;
    const float* qp = qkv + (size_t)s * 384 + g * 16;
    float qv[16];
#pragma unroll
    for (int j = 0; j < 4; j++) {
        float4 t = *(const float4*)(qp + j * 4);
        qv[j*4+0] = t.x; qv[j*4+1] = t.y; qv[j*4+2] = t.z; qv[j*4+3] = t.w;
    }

    const int sh = min(max(h - 1, 0), HD - 3);
    const int sw = min(max(w - 1, 0), HD - 3);
    const int sz = min(max(z - 1, 0), HD - 3);

    float logits[27];
#pragma unroll
    for (int jh = 0; jh < 3; jh++)
    for (int jw = 0; jw < 3; jw++) {
        const int nh = sh + jh, nw = sw + jw;
        __syncthreads();
        const float* src = qkv + ((size_t)((nh * HD + nw) * HD + z)) * 384 + 128 + g * 16;
#pragma unroll
        for (int j = 0; j < 4; j++)
            *(float4*)&slab[z][g * 16 + j * 4] = *(const float4*)(src + j * 4);
        __syncthreads();
#pragma unroll
        for (int jz = 0; jz < 3; jz++) {
            const int nz = sz + jz;
            float dot = 0.f;
#pragma unroll
            for (int d = 0; d < 16; d++) dot += qv[d] * slab[nz][g * 16 + d];
            const int rh = nh - h + 2, rw = nw - w + 2, rz = nz - z + 2;
            logits[(jh * 3 + jw) * 3 + jz] = dot * 0.25f + srpb[g][(rh * 5 + rw) * 5 + rz];
        }
    }

    float mx = logits[0];
#pragma unroll
    for (int j = 1; j < 27; j++) mx = fmaxf(mx, logits[j]);
    float sum = 0.f;
#pragma unroll
    for (int j = 0; j < 27; j++) { logits[j] = __expf(logits[j] - mx); sum += logits[j]; }
    const float inv = 1.f / sum;

    float acc[16];
#pragma unroll
    for (int d = 0; d < 16; d++) acc[d] = 0.f;

#pragma unroll
    for (int jh = 0; jh < 3; jh++)
    for (int jw = 0; jw < 3; jw++) {
        const int nh = sh + jh, nw = sw + jw;
        __syncthreads();
        const float* src = qkv + ((size_t)((nh * HD + nw) * HD + z)) * 384 + 256 + g * 16;
#pragma unroll
        for (int j = 0; j < 4; j++)
            *(float4*)&slab[z][g * 16 + j * 4] = *(const float4*)(src + j * 4);
        __syncthreads();
#pragma unroll
        for (int jz = 0; jz < 3; jz++) {
            const int nz = sz + jz;
            const float p = logits[(jh * 3 + jw) * 3 + jz] * inv;
#pragma unroll
            for (int d = 0; d < 16; d++) acc[d] += p * slab[nz][g * 16 + d];
        }
    }

    float* op = sam + (size_t)s * 128 + g * 16;
#pragma unroll
    for (int j = 0; j < 4; j++) {
        float4 t;
        t.x = acc[j*4+0]; t.y = acc[j*4+1]; t.z = acc[j*4+2]; t.w = acc[j*4+3];
        *(float4*)(op + j * 4) = t;
    }
}

// ---------------- misc kernels ----------------
__global__ void __launch_bounds__(256)
wtrans(const float* __restrict__ w1, const float* __restrict__ w2,
       float* __restrict__ w1t, float* __restrict__ w2t)
{
    int i = blockIdx.x * 256 + threadIdx.x;          // 65536
    int c1 = i >> 9, f1 = i & 511;
    w1t[f1 * 128 + c1] = w1[i];
    int f2 = i >> 7, c2 = i & 127;
    w2t[c2 * 512 + f2] = w2[i];
}

__global__ void __launch_bounds__(1024)
transpose_in(const float* __restrict__ x, float* __restrict__ xt)
{
    __shared__ float t[32][33];
    const int s0 = blockIdx.x * 32, c0 = blockIdx.y * 32;
    const int tx = threadIdx.x, ty = threadIdx.y;
    t[ty][tx] = x[(size_t)(c0 + ty) * S_TOT + s0 + tx];
    __syncthreads();
    xt[(size_t)(s0 + ty) * 128 + c0 + tx] = t[tx][ty];
}

__global__ void __launch_bounds__(128)
stats_partial(const float* __restrict__ Y, float* __restrict__ part)
{
    const int c = threadIdx.x, b = blockIdx.x;
    float s = 0.f, s2 = 0.f;
    const float* p = Y + (size_t)b * 128 * 128;
    for (int r = 0; r < 128; r++) {
        float v = p[r * 128 + c];
        s += v; s2 += v * v;
    }
    part[b * 128 + c] = s;
    part[S_TOT + b * 128 + c] = s2;
}

__global__ void __launch_bounds__(128)
stats_final(const float* __restrict__ part, float* __restrict__ mean,
            float* __restrict__ rstd)
{
    const int c = threadIdx.x;
    float s = 0.f, s2 = 0.f;
    for (int b = 0; b < 256; b++) {
        s  += part[b * 128 + c];
        s2 += part[S_TOT + b * 128 + c];
    }
    const float m = s * (1.f / S_TOT);
    mean[c] = m;
    rstd[c] = rsqrtf(s2 * (1.f / S_TOT) - m * m + 1e-5f);
}

// y1n[s,c] = (y1[s,c]-m[c])*r[c]
__global__ void __launch_bounds__(256)
normalize(const float* __restrict__ y1, const float* __restrict__ m,
          const float* __restrict__ r, float* __restrict__ y1n)
{
    int idx = blockIdx.x * 256 + threadIdx.x;   // 128*32768
    int c = idx & 127;
    y1n[idx] = (y1[idx] - m[c]) * r[c];
}

// skip[c,s] = (t2[s,c]-m2[c])*r2[c] + x[c,s]
__global__ void __launch_bounds__(1024)
finalize2(const float* __restrict__ t2, const float* __restrict__ x,
          const float* __restrict__ m2, const float* __restrict__ r2,
          float* __restrict__ skip)
{
    __shared__ float t[32][33];
    const int s0 = blockIdx.x * 32, c0 = blockIdx.y * 32;
    const int tx = threadIdx.x, ty = threadIdx.y;
    t[ty][tx] = t2[(size_t)(s0 + ty) * 128 + c0 + tx];
    __syncthreads();
    const int c = c0 + ty, s = s0 + tx;
    skip[(size_t)c * S_TOT + s] = (t[tx][ty] - m2[c]) * r2[c] + x[(size_t)c * S_TOT + s];
}

__global__ void __launch_bounds__(256)
maxpool_kernel(const float* __restrict__ skip, float* __restrict__ down)
{
    int idx = blockIdx.x * 256 + threadIdx.x;
    int oz = idx & 15, ow = (idx >> 4) & 15, oh = (idx >> 8) & 15, c = idx >> 12;
    const float* p = skip + (((size_t)c * HD + oh * 2) * HD + ow * 2) * HD + oz * 2;
    float m = p[0];
    m = fmaxf(m, p[1]);
    m = fmaxf(m, p[HD]);           m = fmaxf(m, p[HD + 1]);
    m = fmaxf(m, p[HD * HD]);      m = fmaxf(m, p[HD * HD + 1]);
    m = fmaxf(m, p[HD * HD + HD]); m = fmaxf(m, p[HD * HD + HD + 1]);
    down[idx] = m;
}

// ============================================================
extern "C" void kernel_launch(void* const* d_in, const int* in_sizes, int n_in,
                              void* d_out, int out_size)
{
    const float* x      = (const float*)d_in[0];
    const float* qkv_w  = (const float*)d_in[1];
    const float* qkv_b  = (const float*)d_in[2];
    const float* proj_w = (const float*)d_in[3];
    const float* proj_b = (const float*)d_in[4];
    const float* rpb    = (const float*)d_in[5];
    const float* w1     = (const float*)d_in[6];
    const float* b1     = (const float*)d_in[7];
    const float* w2     = (const float*)d_in[8];
    const float* b2     = (const float*)d_in[9];

    float *xt, *qkv, *sam, *y1, *hid, *t2, *w1t, *w2t, *part, *st;
    cudaGetSymbolAddress((void**)&xt,  g_xt);
    cudaGetSymbolAddress((void**)&qkv, g_qkv);
    cudaGetSymbolAddress((void**)&sam, g_sam);
    cudaGetSymbolAddress((void**)&y1,  g_y1);
    cudaGetSymbolAddress((void**)&hid, g_hid);
    cudaGetSymbolAddress((void**)&t2,  g_t2);
    cudaGetSymbolAddress((void**)&w1t, g_w1t);
    cudaGetSymbolAddress((void**)&w2t, g_w2t);
    cudaGetSymbolAddress((void**)&part,g_part);
    cudaGetSymbolAddress((void**)&st,  g_stats);
    float *m1 = st, *r1 = st + 128, *m2 = st + 256, *r2 = st + 384;
    float *y1n = xt;   // reuse xt after QKV is computed

    const int SMEM = 4 * TILE_F * sizeof(float);   // 73728 B
    cudaFuncSetAttribute(gemm_mma<false,false>,
                         cudaFuncAttributeMaxDynamicSharedMemorySize, SMEM);
    cudaFuncSetAttribute(gemm_mma<true,false>,
                         cudaFuncAttributeMaxDynamicSharedMemorySize, SMEM);
    cudaFuncSetAttribute(gemm_mma<false,true>,
                         cudaFuncAttributeMaxDynamicSharedMemorySize, SMEM);

    // 0) weight transposes + input transpose to [S,C]
    wtrans<<<256, 256>>>(w1, w2, w1t, w2t);
    transpose_in<<<dim3(1024, 4), dim3(32, 32)>>>(x, xt);

    // 1) QKV: [S,384] = xt[S,128] * qkv_w[384,128]^T
    gemm_mma<false,false><<<dim3(256, 3), 256, SMEM>>>(
        xt, qkv_w, qkv, qkv_b, 128, 384, nullptr);

    // 2) neighborhood attention -> sam [S,128]
    attn2<<<dim3(HD, HD), 256>>>(qkv, sam, rpb);

    // 3) proj: [S,128] = sam * proj_w^T
    gemm_mma<false,false><<<dim3(256, 1), 256, SMEM>>>(
        sam, proj_w, y1, proj_b, 128, 128, nullptr);

    // 4) inorm stats of y1, then normalize into y1n (reuses xt)
    stats_partial<<<256, 128>>>(y1, part);
    stats_final<<<1, 128>>>(part, m1, r1);
    normalize<<<(128 * S_TOT) / 256, 256>>>(y1, m1, r1, y1n);

    // 5) MLP fc1 + relu: hid[S,512] = relu(y1n * w1t^T + b1)
    gemm_mma<true,false><<<dim3(256, 4), 256, SMEM>>>(
        y1n, w1t, hid, b1, 128, 512, nullptr);

    // 6) MLP fc2 + residual: t2[S,128] = hid * w2t^T + b2 + y1n
    gemm_mma<false,true><<<dim3(256, 1), 256, SMEM>>>(
        hid, w2t, t2, b2, 512, 128, y1n);

    // 7) inorm stats of t2
    stats_partial<<<256, 128>>>(t2, part);
    stats_final<<<1, 128>>>(part, m2, r2);

    // 8) skip = inorm(t2) + x (back to [C,S]); output = [down | skip]
    float* out  = (float*)d_out;
    float* down = out;
    float* skip = out + 524288;
    finalize2<<<dim3(1024, 4), dim3(32, 32)>>>(t2, x, m2, r2, skip);

    // 9) maxpool
    maxpool_kernel<<<2048, 256>>>(skip, down);
}

// round 4
// speedup vs baseline: 1.7393x; 1.3701x over previous
#include <cuda_runtime.h>
#include <stdint.h>
#include <math.h>

#define S_TOT 32768
#define HD 32

// ---------------- scratch (static device globals) ----------------
__device__ float g_xt  [S_TOT * 128];   // x transposed [S,C]; later reused as y1n
__device__ float g_qkv [S_TOT * 384];   // [S, 384]
__device__ float g_sam [S_TOT * 128];
__device__ float g_y1  [S_TOT * 128];
__device__ float g_hid [S_TOT * 512];
__device__ float g_t2  [S_TOT * 128];
__device__ float g_w1t [512 * 128];
__device__ float g_w2t [128 * 512];
__device__ float g_part[2 * S_TOT];
__device__ float g_stats[512];          // m1,r1,m2,r2

// ---------------- helpers ----------------
__device__ __forceinline__ uint32_t smem_u32(const void* p) {
    uint32_t a;
    asm("{ .reg .u64 t; cvta.to.shared.u64 t, %1; cvt.u32.u64 %0, t; }"
        : "=r"(a) : "l"(p));
    return a;
}
__device__ __forceinline__ void cp16(uint32_t s, const void* g) {
    asm volatile("cp.async.cg.shared.global [%0], [%1], 16;" :: "r"(s), "l"(g));
}
__device__ __forceinline__ void cp_commit() {
    asm volatile("cp.async.commit_group;" ::: "memory");
}
template<int N>
__device__ __forceinline__ void cp_wait() {
    asm volatile("cp.async.wait_group %0;" :: "n"(N) : "memory");
}
__device__ __forceinline__ uint32_t f2tf32(float f) {
    uint32_t u;
    asm("cvt.rna.tf32.f32 %0, %1;" : "=r"(u) : "f"(f));
    return u;
}

// ============================================================
// tf32 mma.sync GEMM: Y[s0..s0+128, n0..n0+128) = A[S,Kd] * B[N,Kd]^T
// CTA 128x128, 8 warps (2 M x 4 N), warp tile 64x32, K-chunk 32,
// cp.async double buffer. smem row stride 36 floats (conflict-free frags).
// ============================================================
#define KSTR 36
#define TILE_F (128 * KSTR)

template<bool RELU, bool RESID>
__global__ void __launch_bounds__(256)
gemm_mma(const float* __restrict__ A, const float* __restrict__ B,
         float* __restrict__ Y, const float* __restrict__ bias,
         int Kd, int Nout, const float* __restrict__ resid)
{
    extern __shared__ float dsm[];
    float* sA[2] = { dsm,            dsm + 2 * TILE_F };
    float* sB[2] = { dsm + TILE_F,   dsm + 3 * TILE_F };

    const int tid = threadIdx.x;
    const int wid = tid >> 5;
    const int lane = tid & 31;
    const int wm = wid & 1;
    const int wn = wid >> 1;
    const int rq = lane >> 2;
    const int cq = lane & 3;
    const int s0 = blockIdx.x * 128;
    const int n0 = blockIdx.y * 128;

    const int nch = Kd >> 5;

    float acc[4][4][4];
#pragma unroll
    for (int mi = 0; mi < 4; mi++)
#pragma unroll
        for (int ni = 0; ni < 4; ni++)
#pragma unroll
            for (int r = 0; r < 4; r++) acc[mi][ni][r] = 0.f;

    auto load_chunk = [&](int ci, int buf) {
        const int kc = ci << 5;
        uint32_t aBase = smem_u32(sA[buf]);
        uint32_t bBase = smem_u32(sB[buf]);
#pragma unroll
        for (int j = 0; j < 4; j++) {
            int idx = tid + j * 256;
            int row = idx >> 3, seg = idx & 7;
            cp16(aBase + (row * KSTR + seg * 4) * 4,
                 &A[(size_t)(s0 + row) * Kd + kc + seg * 4]);
            cp16(bBase + (row * KSTR + seg * 4) * 4,
                 &B[(size_t)(n0 + row) * Kd + kc + seg * 4]);
        }
        cp_commit();
    };

    load_chunk(0, 0);

    for (int ci = 0; ci < nch; ci++) {
        if (ci + 1 < nch) { load_chunk(ci + 1, (ci + 1) & 1); cp_wait<1>(); }
        else              { cp_wait<0>(); }
        __syncthreads();

        const float* pA = sA[ci & 1] + wm * 64 * KSTR;
        const float* pB = sB[ci & 1] + wn * 32 * KSTR;

#pragma unroll
        for (int ks = 0; ks < 4; ks++) {
            const int kof = ks * 8 + cq;
            uint32_t a[4][4], b[4][2];
#pragma unroll
            for (int mi = 0; mi < 4; mi++) {
                const float* p = pA + (mi * 16 + rq) * KSTR + kof;
                a[mi][0] = f2tf32(p[0]);
                a[mi][1] = f2tf32(p[8 * KSTR]);
                a[mi][2] = f2tf32(p[4]);
                a[mi][3] = f2tf32(p[8 * KSTR + 4]);
            }
#pragma unroll
            for (int ni = 0; ni < 4; ni++) {
                const float* p = pB + (ni * 8 + rq) * KSTR + kof;
                b[ni][0] = f2tf32(p[0]);
                b[ni][1] = f2tf32(p[4]);
            }
#pragma unroll
            for (int mi = 0; mi < 4; mi++)
#pragma unroll
                for (int ni = 0; ni < 4; ni++) {
                    asm volatile(
                        "mma.sync.aligned.m16n8k8.row.col.f32.tf32.tf32.f32 "
                        "{%0,%1,%2,%3}, {%4,%5,%6,%7}, {%8,%9}, {%0,%1,%2,%3};"
                        : "+f"(acc[mi][ni][0]), "+f"(acc[mi][ni][1]),
                          "+f"(acc[mi][ni][2]), "+f"(acc[mi][ni][3])
                        : "r"(a[mi][0]), "r"(a[mi][1]), "r"(a[mi][2]), "r"(a[mi][3]),
                          "r"(b[ni][0]), "r"(b[ni][1]));
                }
        }
        __syncthreads();
    }

#pragma unroll
    for (int ni = 0; ni < 4; ni++) {
        const int col = n0 + wn * 32 + ni * 8 + cq * 2;
        const float b0 = bias[col], b1 = bias[col + 1];
#pragma unroll
        for (int mi = 0; mi < 4; mi++) {
            const int row0 = s0 + wm * 64 + mi * 16 + rq;
#pragma unroll
            for (int half = 0; half < 2; half++) {
                const int row = row0 + half * 8;
                float v0 = acc[mi][ni][half * 2 + 0] + b0;
                float v1 = acc[mi][ni][half * 2 + 1] + b1;
                if (RELU) { v0 = fmaxf(v0, 0.f); v1 = fmaxf(v1, 0.f); }
                if (RESID) {
                    const float* rp = resid + (size_t)row * 128 + col;
                    v0 += rp[0]; v1 += rp[1];
                }
                float2 o; o.x = v0; o.y = v1;
                *(float2*)&Y[(size_t)row * Nout + col] = o;
            }
        }
    }
}

// ============================================================
// Neighborhood attention, conflict-free smem version.
// block = 256 (warp = group g, lane = z), grid = (w, h).
// slab[32][132]: LDS.128 at addr 132*nz + 16*g + 4j is conflict-free
// (per 8-lane phase, start banks 4*lane mod 32 cover all 32 banks once).
// ============================================================
#define SLAB_STR 132

__global__ void __launch_bounds__(256)
attn3(const float* __restrict__ qkv, float* __restrict__ sam,
      const float* __restrict__ rpb)
{
    __shared__ __align__(16) float slab[32 * SLAB_STR];
    __shared__ float srpb[1000];

    const int h = blockIdx.y, w = blockIdx.x;
    const int tid = threadIdx.x;
    const int g = tid >> 5;          // warp = head group
    const int z = tid & 31;          // lane = z

    for (int i = tid; i < 1000; i += 256) srpb[i] = rpb[i];

    const int c4 = tid & 31;         // fill mapping pieces
    // fill: slab[zz][0..127] <- qkv[row(nh,nw,zz)*384 + off + c]
    auto fill = [&](int nh, int nw, int off) {
        const float* src = qkv + ((size_t)((nh * HD + nw) * HD)) * 384 + off;
#pragma unroll
        for (int i = 0; i < 4; i++) {
            const int idx = tid + i * 256;
            const int zz = idx >> 5;
            float4 v = *(const float4*)(src + (size_t)zz * 384 + c4 * 4);
            *(float4*)&slab[zz * SLAB_STR + c4 * 4] = v;
        }
    };

    // ---- Q into registers via slab ----
    fill(h, w, 0);
    __syncthreads();
    float qv[16];
#pragma unroll
    for (int j = 0; j < 4; j++) {
        float4 t = *(const float4*)&slab[z * SLAB_STR + g * 16 + j * 4];
        qv[j*4+0] = t.x; qv[j*4+1] = t.y; qv[j*4+2] = t.z; qv[j*4+3] = t.w;
    }

    const int sh = min(max(h - 1, 0), HD - 3);
    const int sw = min(max(w - 1, 0), HD - 3);
    const int sz = min(max(z - 1, 0), HD - 3);

    float logits[27];
#pragma unroll
    for (int jh = 0; jh < 3; jh++)
#pragma unroll
    for (int jw = 0; jw < 3; jw++) {
        const int nh = sh + jh, nw = sw + jw;
        __syncthreads();
        fill(nh, nw, 128);
        __syncthreads();
        const int rh = nh - h + 2, rw = nw - w + 2;
#pragma unroll
        for (int jz = 0; jz < 3; jz++) {
            const int nz = sz + jz;
            float dot = 0.f;
#pragma unroll
            for (int j = 0; j < 4; j++) {
                float4 kk = *(const float4*)&slab[nz * SLAB_STR + g * 16 + j * 4];
                dot += qv[j*4+0] * kk.x + qv[j*4+1] * kk.y
                     + qv[j*4+2] * kk.z + qv[j*4+3] * kk.w;
            }
            logits[(jh * 3 + jw) * 3 + jz] =
                dot * 0.25f + srpb[g * 125 + (rh * 5 + rw) * 5 + (nz - z + 2)];
        }
    }

    float mx = logits[0];
#pragma unroll
    for (int j = 1; j < 27; j++) mx = fmaxf(mx, logits[j]);
    float sum = 0.f;
#pragma unroll
    for (int j = 0; j < 27; j++) { logits[j] = __expf(logits[j] - mx); sum += logits[j]; }
    const float inv = 1.f / sum;

    float acc[16];
#pragma unroll
    for (int d = 0; d < 16; d++) acc[d] = 0.f;

#pragma unroll
    for (int jh = 0; jh < 3; jh++)
#pragma unroll
    for (int jw = 0; jw < 3; jw++) {
        const int nh = sh + jh, nw = sw + jw;
        __syncthreads();
        fill(nh, nw, 256);
        __syncthreads();
#pragma unroll
        for (int jz = 0; jz < 3; jz++) {
            const int nz = sz + jz;
            const float p = logits[(jh * 3 + jw) * 3 + jz] * inv;
#pragma unroll
            for (int j = 0; j < 4; j++) {
                float4 vv = *(const float4*)&slab[nz * SLAB_STR + g * 16 + j * 4];
                acc[j*4+0] += p * vv.x; acc[j*4+1] += p * vv.y;
                acc[j*4+2] += p * vv.z; acc[j*4+3] += p * vv.w;
            }
        }
    }

    // ---- store via slab for coalesced writes ----
    __syncthreads();
#pragma unroll
    for (int j = 0; j < 4; j++) {
        float4 t;
        t.x = acc[j*4+0]; t.y = acc[j*4+1]; t.z = acc[j*4+2]; t.w = acc[j*4+3];
        *(float4*)&slab[z * SLAB_STR + g * 16 + j * 4] = t;
    }
    __syncthreads();
    {
        float* dst = sam + ((size_t)((h * HD + w) * HD)) * 128;
#pragma unroll
        for (int i = 0; i < 4; i++) {
            const int idx = tid + i * 256;
            const int zz = idx >> 5;
            float4 v = *(const float4*)&slab[zz * SLAB_STR + c4 * 4];
            *(float4*)&dst[(size_t)zz * 128 + c4 * 4] = v;
        }
    }
}

// ---------------- misc kernels ----------------
__global__ void __launch_bounds__(256)
wtrans(const float* __restrict__ w1, const float* __restrict__ w2,
       float* __restrict__ w1t, float* __restrict__ w2t)
{
    int i = blockIdx.x * 256 + threadIdx.x;
    int c1 = i >> 9, f1 = i & 511;
    w1t[f1 * 128 + c1] = w1[i];
    int f2 = i >> 7, c2 = i & 127;
    w2t[c2 * 512 + f2] = w2[i];
}

__global__ void __launch_bounds__(1024)
transpose_in(const float* __restrict__ x, float* __restrict__ xt)
{
    __shared__ float t[32][33];
    const int s0 = blockIdx.x * 32, c0 = blockIdx.y * 32;
    const int tx = threadIdx.x, ty = threadIdx.y;
    t[ty][tx] = x[(size_t)(c0 + ty) * S_TOT + s0 + tx];
    __syncthreads();
    xt[(size_t)(s0 + ty) * 128 + c0 + tx] = t[tx][ty];
}

__global__ void __launch_bounds__(128)
stats_partial(const float* __restrict__ Y, float* __restrict__ part)
{
    const int c = threadIdx.x, b = blockIdx.x;
    float s = 0.f, s2 = 0.f;
    const float* p = Y + (size_t)b * 128 * 128;
    for (int r = 0; r < 128; r++) {
        float v = p[r * 128 + c];
        s += v; s2 += v * v;
    }
    part[b * 128 + c] = s;
    part[S_TOT + b * 128 + c] = s2;
}

__global__ void __launch_bounds__(128)
stats_final(const float* __restrict__ part, float* __restrict__ mean,
            float* __restrict__ rstd)
{
    const int c = threadIdx.x;
    float s = 0.f, s2 = 0.f;
    for (int b = 0; b < 256; b++) {
        s  += part[b * 128 + c];
        s2 += part[S_TOT + b * 128 + c];
    }
    const float m = s * (1.f / S_TOT);
    mean[c] = m;
    rstd[c] = rsqrtf(s2 * (1.f / S_TOT) - m * m + 1e-5f);
}

__global__ void __launch_bounds__(256)
normalize(const float* __restrict__ y1, const float* __restrict__ m,
          const float* __restrict__ r, float* __restrict__ y1n)
{
    int idx = blockIdx.x * 256 + threadIdx.x;
    int c = idx & 127;
    y1n[idx] = (y1[idx] - m[c]) * r[c];
}

__global__ void __launch_bounds__(1024)
finalize2(const float* __restrict__ t2, const float* __restrict__ x,
          const float* __restrict__ m2, const float* __restrict__ r2,
          float* __restrict__ skip)
{
    __shared__ float t[32][33];
    const int s0 = blockIdx.x * 32, c0 = blockIdx.y * 32;
    const int tx = threadIdx.x, ty = threadIdx.y;
    t[ty][tx] = t2[(size_t)(s0 + ty) * 128 + c0 + tx];
    __syncthreads();
    const int c = c0 + ty, s = s0 + tx;
    skip[(size_t)c * S_TOT + s] = (t[tx][ty] - m2[c]) * r2[c] + x[(size_t)c * S_TOT + s];
}

__global__ void __launch_bounds__(256)
maxpool_kernel(const float* __restrict__ skip, float* __restrict__ down)
{
    int idx = blockIdx.x * 256 + threadIdx.x;
    int oz = idx & 15, ow = (idx >> 4) & 15, oh = (idx >> 8) & 15, c = idx >> 12;
    const float* p = skip + (((size_t)c * HD + oh * 2) * HD + ow * 2) * HD + oz * 2;
    float m = p[0];
    m = fmaxf(m, p[1]);
    m = fmaxf(m, p[HD]);           m = fmaxf(m, p[HD + 1]);
    m = fmaxf(m, p[HD * HD]);      m = fmaxf(m, p[HD * HD + 1]);
    m = fmaxf(m, p[HD * HD + HD]); m = fmaxf(m, p[HD * HD + HD + 1]);
    down[idx] = m;
}

// ============================================================
extern "C" void kernel_launch(void* const* d_in, const int* in_sizes, int n_in,
                              void* d_out, int out_size)
{
    const float* x      = (const float*)d_in[0];
    const float* qkv_w  = (const float*)d_in[1];
    const float* qkv_b  = (const float*)d_in[2];
    const float* proj_w = (const float*)d_in[3];
    const float* proj_b = (const float*)d_in[4];
    const float* rpb    = (const float*)d_in[5];
    const float* w1     = (const float*)d_in[6];
    const float* b1     = (const float*)d_in[7];
    const float* w2     = (const float*)d_in[8];
    const float* b2     = (const float*)d_in[9];

    float *xt, *qkv, *sam, *y1, *hid, *t2, *w1t, *w2t, *part, *st;
    cudaGetSymbolAddress((void**)&xt,  g_xt);
    cudaGetSymbolAddress((void**)&qkv, g_qkv);
    cudaGetSymbolAddress((void**)&sam, g_sam);
    cudaGetSymbolAddress((void**)&y1,  g_y1);
    cudaGetSymbolAddress((void**)&hid, g_hid);
    cudaGetSymbolAddress((void**)&t2,  g_t2);
    cudaGetSymbolAddress((void**)&w1t, g_w1t);
    cudaGetSymbolAddress((void**)&w2t, g_w2t);
    cudaGetSymbolAddress((void**)&part,g_part);
    cudaGetSymbolAddress((void**)&st,  g_stats);
    float *m1 = st, *r1 = st + 128, *m2 = st + 256, *r2 = st + 384;
    float *y1n = xt;

    const int SMEM = 4 * TILE_F * sizeof(float);
    cudaFuncSetAttribute(gemm_mma<false,false>,
                         cudaFuncAttributeMaxDynamicSharedMemorySize, SMEM);
    cudaFuncSetAttribute(gemm_mma<true,false>,
                         cudaFuncAttributeMaxDynamicSharedMemorySize, SMEM);
    cudaFuncSetAttribute(gemm_mma<false,true>,
                         cudaFuncAttributeMaxDynamicSharedMemorySize, SMEM);

    wtrans<<<256, 256>>>(w1, w2, w1t, w2t);
    transpose_in<<<dim3(1024, 4), dim3(32, 32)>>>(x, xt);

    gemm_mma<false,false><<<dim3(256, 3), 256, SMEM>>>(
        xt, qkv_w, qkv, qkv_b, 128, 384, nullptr);

    attn3<<<dim3(HD, HD), 256>>>(qkv, sam, rpb);

    gemm_mma<false,false><<<dim3(256, 1), 256, SMEM>>>(
        sam, proj_w, y1, proj_b, 128, 128, nullptr);

    stats_partial<<<256, 128>>>(y1, part);
    stats_final<<<1, 128>>>(part, m1, r1);
    normalize<<<(128 * S_TOT) / 256, 256>>>(y1, m1, r1, y1n);

    gemm_mma<true,false><<<dim3(256, 4), 256, SMEM>>>(
        y1n, w1t, hid, b1, 128, 512, nullptr);

    gemm_mma<false,true><<<dim3(256, 1), 256, SMEM>>>(
        hid, w2t, t2, b2, 512, 128, y1n);

    stats_partial<<<256, 128>>>(t2, part);
    stats_final<<<1, 128>>>(part, m2, r2);

    float* out  = (float*)d_out;
    float* down = out;
    float* skip = out + 524288;
    finalize2<<<dim3(1024, 4), dim3(32, 32)>>>(t2, x, m2, r2, skip);

    maxpool_kernel<<<2048, 256>>>(skip, down);
}

// round 5
// speedup vs baseline: 2.0622x; 1.1856x over previous
#include <cuda_runtime.h>
#include <stdint.h>
#include <math.h>

#define S_TOT 32768
#define HD 32

// ---------------- scratch (static device globals) ----------------
__device__ float g_xt  [S_TOT * 128];   // x transposed [S,C]
__device__ float g_qkv [S_TOT * 384];
__device__ float g_sam [S_TOT * 128];
__device__ float g_y1  [S_TOT * 128];
__device__ float g_hid [S_TOT * 512];
__device__ float g_t2  [S_TOT * 128];
__device__ float g_w1f [512 * 128];     // folded fc1 weights [f][c]
__device__ float g_w2t [128 * 512];
__device__ float g_b1f [512];
__device__ float g_part[2 * S_TOT];
__device__ float g_stats[512];          // m1,r1,m2,r2

// ---------------- helpers ----------------
__device__ __forceinline__ uint32_t smem_u32(const void* p) {
    uint32_t a;
    asm("{ .reg .u64 t; cvta.to.shared.u64 t, %1; cvt.u32.u64 %0, t; }"
        : "=r"(a) : "l"(p));
    return a;
}
__device__ __forceinline__ void cp16(uint32_t s, const void* g) {
    asm volatile("cp.async.cg.shared.global [%0], [%1], 16;" :: "r"(s), "l"(g));
}
__device__ __forceinline__ void cp_commit() {
    asm volatile("cp.async.commit_group;" ::: "memory");
}
template<int N>
__device__ __forceinline__ void cp_wait() {
    asm volatile("cp.async.wait_group %0;" :: "n"(N) : "memory");
}
__device__ __forceinline__ uint32_t f2tf32(float f) {
    uint32_t u;
    asm("cvt.rna.tf32.f32 %0, %1;" : "=r"(u) : "f"(f));
    return u;
}

// ============================================================
// tf32 mma.sync GEMM: Y[s0..+128, n0..+128) = A[S,Kd] * B[N,Kd]^T
// 128 threads, 4 warps (2M x 2N), warp tile 64x64, K-chunk 32,
// 3-stage cp.async pipeline. smem row stride 36 (conflict-free).
// RESID: Y += (resid - mr[col]) * rr[col]
// ============================================================
#define KSTR 36
#define TILE_F (128 * KSTR)          // 4608 floats = 18432 B per tile

template<bool RELU, bool RESID>
__global__ void __launch_bounds__(128)
gemm_mma(const float* __restrict__ A, const float* __restrict__ B,
         float* __restrict__ Y, const float* __restrict__ bias,
         int Kd, int Nout, const float* __restrict__ resid,
         const float* __restrict__ mr, const float* __restrict__ rr)
{
    extern __shared__ float dsm[];

    const int tid = threadIdx.x;
    const int wid = tid >> 5;
    const int lane = tid & 31;
    const int wm = wid & 1;          // M warp (2)
    const int wn = wid >> 1;         // N warp (2)
    const int rq = lane >> 2;
    const int cq = lane & 3;
    const int s0 = blockIdx.x * 128;
    const int n0 = blockIdx.y * 128;

    const int nch = Kd >> 5;

    float acc[4][8][4];
#pragma unroll
    for (int mi = 0; mi < 4; mi++)
#pragma unroll
        for (int ni = 0; ni < 8; ni++)
#pragma unroll
            for (int r = 0; r < 4; r++) acc[mi][ni][r] = 0.f;

    auto load_chunk = [&](int ci, int buf) {
        const int kc = ci << 5;
        float* sA = dsm + buf * 2 * TILE_F;
        float* sB = sA + TILE_F;
        uint32_t aBase = smem_u32(sA);
        uint32_t bBase = smem_u32(sB);
#pragma unroll
        for (int j = 0; j < 8; j++) {
            int idx = tid + j * 128;          // 0..1023
            int row = idx >> 3, seg = idx & 7;
            cp16(aBase + (row * KSTR + seg * 4) * 4,
                 &A[(size_t)(s0 + row) * Kd + kc + seg * 4]);
            cp16(bBase + (row * KSTR + seg * 4) * 4,
                 &B[(size_t)(n0 + row) * Kd + kc + seg * 4]);
        }
        cp_commit();
    };

    load_chunk(0, 0);
    load_chunk(1, 1);

    for (int ci = 0; ci < nch; ci++) {
        if (ci + 2 < nch)      { load_chunk(ci + 2, (ci + 2) % 3); cp_wait<2>(); }
        else if (ci + 1 < nch) { cp_wait<1>(); }
        else                   { cp_wait<0>(); }
        __syncthreads();

        const float* sA = dsm + (ci % 3) * 2 * TILE_F;
        const float* pA = sA + wm * 64 * KSTR;
        const float* pB = sA + TILE_F + wn * 64 * KSTR;

#pragma unroll
        for (int ks = 0; ks < 4; ks++) {
            const int kof = ks * 8 + cq;
            uint32_t a[4][4], b[8][2];
#pragma unroll
            for (int mi = 0; mi < 4; mi++) {
                const float* p = pA + (mi * 16 + rq) * KSTR + kof;
                a[mi][0] = f2tf32(p[0]);
                a[mi][1] = f2tf32(p[8 * KSTR]);
                a[mi][2] = f2tf32(p[4]);
                a[mi][3] = f2tf32(p[8 * KSTR + 4]);
            }
#pragma unroll
            for (int ni = 0; ni < 8; ni++) {
                const float* p = pB + (ni * 8 + rq) * KSTR + kof;
                b[ni][0] = f2tf32(p[0]);
                b[ni][1] = f2tf32(p[4]);
            }
#pragma unroll
            for (int mi = 0; mi < 4; mi++)
#pragma unroll
                for (int ni = 0; ni < 8; ni++) {
                    asm volatile(
                        "mma.sync.aligned.m16n8k8.row.col.f32.tf32.tf32.f32 "
                        "{%0,%1,%2,%3}, {%4,%5,%6,%7}, {%8,%9}, {%0,%1,%2,%3};"
                        : "+f"(acc[mi][ni][0]), "+f"(acc[mi][ni][1]),
                          "+f"(acc[mi][ni][2]), "+f"(acc[mi][ni][3])
                        : "r"(a[mi][0]), "r"(a[mi][1]), "r"(a[mi][2]), "r"(a[mi][3]),
                          "r"(b[ni][0]), "r"(b[ni][1]));
                }
        }
        __syncthreads();
    }

    // ---- epilogue ----
#pragma unroll
    for (int ni = 0; ni < 8; ni++) {
        const int col = n0 + wn * 64 + ni * 8 + cq * 2;
        const float b0 = bias[col], b1 = bias[col + 1];
        float m0 = 0.f, m1 = 0.f, r0 = 0.f, r1 = 0.f;
        if (RESID) { m0 = mr[col]; m1 = mr[col + 1]; r0 = rr[col]; r1 = rr[col + 1]; }
#pragma unroll
        for (int mi = 0; mi < 4; mi++) {
            const int row0 = s0 + wm * 64 + mi * 16 + rq;
#pragma unroll
            for (int half = 0; half < 2; half++) {
                const int row = row0 + half * 8;
                float v0 = acc[mi][ni][half * 2 + 0] + b0;
                float v1 = acc[mi][ni][half * 2 + 1] + b1;
                if (RELU) { v0 = fmaxf(v0, 0.f); v1 = fmaxf(v1, 0.f); }
                if (RESID) {
                    const float* rp = resid + (size_t)row * 128 + col;
                    v0 += (rp[0] - m0) * r0;
                    v1 += (rp[1] - m1) * r1;
                }
                float2 o; o.x = v0; o.y = v1;
                *(float2*)&Y[(size_t)row * Nout + col] = o;
            }
        }
    }
}

// ============================================================
// Neighborhood attention (R4 conflict-free version, unchanged)
// ============================================================
#define SLAB_STR 132

__global__ void __launch_bounds__(256)
attn3(const float* __restrict__ qkv, float* __restrict__ sam,
      const float* __restrict__ rpb)
{
    __shared__ __align__(16) float slab[32 * SLAB_STR];
    __shared__ float srpb[1000];

    const int h = blockIdx.y, w = blockIdx.x;
    const int tid = threadIdx.x;
    const int g = tid >> 5;
    const int z = tid & 31;

    for (int i = tid; i < 1000; i += 256) srpb[i] = rpb[i];

    const int c4 = tid & 31;
    auto fill = [&](int nh, int nw, int off) {
        const float* src = qkv + ((size_t)((nh * HD + nw) * HD)) * 384 + off;
#pragma unroll
        for (int i = 0; i < 4; i++) {
            const int idx = tid + i * 256;
            const int zz = idx >> 5;
            float4 v = *(const float4*)(src + (size_t)zz * 384 + c4 * 4);
            *(float4*)&slab[zz * SLAB_STR + c4 * 4] = v;
        }
    };

    fill(h, w, 0);
    __syncthreads();
    float qv[16];
#pragma unroll
    for (int j = 0; j < 4; j++) {
        float4 t = *(const float4*)&slab[z * SLAB_STR + g * 16 + j * 4];
        qv[j*4+0] = t.x; qv[j*4+1] = t.y; qv[j*4+2] = t.z; qv[j*4+3] = t.w;
    }

    const int sh = min(max(h - 1, 0), HD - 3);
    const int sw = min(max(w - 1, 0), HD - 3);
    const int sz = min(max(z - 1, 0), HD - 3);

    float logits[27];
#pragma unroll
    for (int jh = 0; jh < 3; jh++)
#pragma unroll
    for (int jw = 0; jw < 3; jw++) {
        const int nh = sh + jh, nw = sw + jw;
        __syncthreads();
        fill(nh, nw, 128);
        __syncthreads();
        const int rh = nh - h + 2, rw = nw - w + 2;
#pragma unroll
        for (int jz = 0; jz < 3; jz++) {
            const int nz = sz + jz;
            float dot = 0.f;
#pragma unroll
            for (int j = 0; j < 4; j++) {
                float4 kk = *(const float4*)&slab[nz * SLAB_STR + g * 16 + j * 4];
                dot += qv[j*4+0] * kk.x + qv[j*4+1] * kk.y
                     + qv[j*4+2] * kk.z + qv[j*4+3] * kk.w;
            }
            logits[(jh * 3 + jw) * 3 + jz] =
                dot * 0.25f + srpb[g * 125 + (rh * 5 + rw) * 5 + (nz - z + 2)];
        }
    }

    float mx = logits[0];
#pragma unroll
    for (int j = 1; j < 27; j++) mx = fmaxf(mx, logits[j]);
    float sum = 0.f;
#pragma unroll
    for (int j = 0; j < 27; j++) { logits[j] = __expf(logits[j] - mx); sum += logits[j]; }
    const float inv = 1.f / sum;

    float acc[16];
#pragma unroll
    for (int d = 0; d < 16; d++) acc[d] = 0.f;

#pragma unroll
    for (int jh = 0; jh < 3; jh++)
#pragma unroll
    for (int jw = 0; jw < 3; jw++) {
        const int nh = sh + jh, nw = sw + jw;
        __syncthreads();
        fill(nh, nw, 256);
        __syncthreads();
#pragma unroll
        for (int jz = 0; jz < 3; jz++) {
            const int nz = sz + jz;
            const float p = logits[(jh * 3 + jw) * 3 + jz] * inv;
#pragma unroll
            for (int j = 0; j < 4; j++) {
                float4 vv = *(const float4*)&slab[nz * SLAB_STR + g * 16 + j * 4];
                acc[j*4+0] += p * vv.x; acc[j*4+1] += p * vv.y;
                acc[j*4+2] += p * vv.z; acc[j*4+3] += p * vv.w;
            }
        }
    }

    __syncthreads();
#pragma unroll
    for (int j = 0; j < 4; j++) {
        float4 t;
        t.x = acc[j*4+0]; t.y = acc[j*4+1]; t.z = acc[j*4+2]; t.w = acc[j*4+3];
        *(float4*)&slab[z * SLAB_STR + g * 16 + j * 4] = t;
    }
    __syncthreads();
    {
        float* dst = sam + ((size_t)((h * HD + w) * HD)) * 128;
#pragma unroll
        for (int i = 0; i < 4; i++) {
            const int idx = tid + i * 256;
            const int zz = idx >> 5;
            float4 v = *(const float4*)&slab[zz * SLAB_STR + c4 * 4];
            *(float4*)&dst[(size_t)zz * 128 + c4 * 4] = v;
        }
    }
}

// ---------------- misc kernels ----------------
__global__ void __launch_bounds__(256)
w2trans(const float* __restrict__ w2, float* __restrict__ w2t)
{
    int i = blockIdx.x * 256 + threadIdx.x;   // 65536
    int f = i >> 7, c = i & 127;
    w2t[c * 512 + f] = w2[i];
}

// fold inorm(m1,r1) into fc1: w1f[f][c] = w1[c][f]*r1[c];
// b1f[f] = b1[f] - sum_c w1[c][f]*r1[c]*m1[c]
__global__ void __launch_bounds__(128)
w1fold(const float* __restrict__ w1, const float* __restrict__ b1,
       const float* __restrict__ m1, const float* __restrict__ r1,
       float* __restrict__ w1f, float* __restrict__ b1f)
{
    const int f = blockIdx.x, c = threadIdx.x;
    float wv = w1[c * 512 + f] * r1[c];
    w1f[f * 128 + c] = wv;
    __shared__ float sh[128];
    sh[c] = wv * m1[c];
    __syncthreads();
    for (int o = 64; o > 0; o >>= 1) {
        if (c < o) sh[c] += sh[c + o];
        __syncthreads();
    }
    if (c == 0) b1f[f] = b1[f] - sh[0];
}

__global__ void __launch_bounds__(1024)
transpose_in(const float* __restrict__ x, float* __restrict__ xt)
{
    __shared__ float t[32][33];
    const int s0 = blockIdx.x * 32, c0 = blockIdx.y * 32;
    const int tx = threadIdx.x, ty = threadIdx.y;
    t[ty][tx] = x[(size_t)(c0 + ty) * S_TOT + s0 + tx];
    __syncthreads();
    xt[(size_t)(s0 + ty) * 128 + c0 + tx] = t[tx][ty];
}

__global__ void __launch_bounds__(128)
stats_partial(const float* __restrict__ Y, float* __restrict__ part)
{
    const int c = threadIdx.x, b = blockIdx.x;
    float s = 0.f, s2 = 0.f;
    const float* p = Y + (size_t)b * 128 * 128;
    for (int r = 0; r < 128; r++) {
        float v = p[r * 128 + c];
        s += v; s2 += v * v;
    }
    part[b * 128 + c] = s;
    part[S_TOT + b * 128 + c] = s2;
}

__global__ void __launch_bounds__(128)
stats_final(const float* __restrict__ part, float* __restrict__ mean,
            float* __restrict__ rstd)
{
    const int c = threadIdx.x;
    float s = 0.f, s2 = 0.f;
    for (int b = 0; b < 256; b++) {
        s  += part[b * 128 + c];
        s2 += part[S_TOT + b * 128 + c];
    }
    const float m = s * (1.f / S_TOT);
    mean[c] = m;
    rstd[c] = rsqrtf(s2 * (1.f / S_TOT) - m * m + 1e-5f);
}

__global__ void __launch_bounds__(1024)
finalize2(const float* __restrict__ t2, const float* __restrict__ x,
          const float* __restrict__ m2, const float* __restrict__ r2,
          float* __restrict__ skip)
{
    __shared__ float t[32][33];
    const int s0 = blockIdx.x * 32, c0 = blockIdx.y * 32;
    const int tx = threadIdx.x, ty = threadIdx.y;
    t[ty][tx] = t2[(size_t)(s0 + ty) * 128 + c0 + tx];
    __syncthreads();
    const int c = c0 + ty, s = s0 + tx;
    skip[(size_t)c * S_TOT + s] = (t[tx][ty] - m2[c]) * r2[c] + x[(size_t)c * S_TOT + s];
}

__global__ void __launch_bounds__(256)
maxpool_kernel(const float* __restrict__ skip, float* __restrict__ down)
{
    int idx = blockIdx.x * 256 + threadIdx.x;
    int oz = idx & 15, ow = (idx >> 4) & 15, oh = (idx >> 8) & 15, c = idx >> 12;
    const float* p = skip + (((size_t)c * HD + oh * 2) * HD + ow * 2) * HD + oz * 2;
    float m = p[0];
    m = fmaxf(m, p[1]);
    m = fmaxf(m, p[HD]);           m = fmaxf(m, p[HD + 1]);
    m = fmaxf(m, p[HD * HD]);      m = fmaxf(m, p[HD * HD + 1]);
    m = fmaxf(m, p[HD * HD + HD]); m = fmaxf(m, p[HD * HD + HD + 1]);
    down[idx] = m;
}

// ============================================================
extern "C" void kernel_launch(void* const* d_in, const int* in_sizes, int n_in,
                              void* d_out, int out_size)
{
    const float* x      = (const float*)d_in[0];
    const float* qkv_w  = (const float*)d_in[1];
    const float* qkv_b  = (const float*)d_in[2];
    const float* proj_w = (const float*)d_in[3];
    const float* proj_b = (const float*)d_in[4];
    const float* rpb    = (const float*)d_in[5];
    const float* w1     = (const float*)d_in[6];
    const float* b1     = (const float*)d_in[7];
    const float* w2     = (const float*)d_in[8];
    const float* b2     = (const float*)d_in[9];

    float *xt, *qkv, *sam, *y1, *hid, *t2, *w1f, *w2t, *b1f, *part, *st;
    cudaGetSymbolAddress((void**)&xt,  g_xt);
    cudaGetSymbolAddress((void**)&qkv, g_qkv);
    cudaGetSymbolAddress((void**)&sam, g_sam);
    cudaGetSymbolAddress((void**)&y1,  g_y1);
    cudaGetSymbolAddress((void**)&hid, g_hid);
    cudaGetSymbolAddress((void**)&t2,  g_t2);
    cudaGetSymbolAddress((void**)&w1f, g_w1f);
    cudaGetSymbolAddress((void**)&w2t, g_w2t);
    cudaGetSymbolAddress((void**)&b1f, g_b1f);
    cudaGetSymbolAddress((void**)&part,g_part);
    cudaGetSymbolAddress((void**)&st,  g_stats);
    float *m1 = st, *r1 = st + 128, *m2 = st + 256, *r2 = st + 384;

    const int SMEM = 3 * 2 * TILE_F * sizeof(float);   // 110592 B
    cudaFuncSetAttribute(gemm_mma<false,false>,
                         cudaFuncAttributeMaxDynamicSharedMemorySize, SMEM);
    cudaFuncSetAttribute(gemm_mma<true,false>,
                         cudaFuncAttributeMaxDynamicSharedMemorySize, SMEM);
    cudaFuncSetAttribute(gemm_mma<false,true>,
                         cudaFuncAttributeMaxDynamicSharedMemorySize, SMEM);

    // prep: w2 transpose + input transpose to [S,C]
    w2trans<<<256, 256>>>(w2, w2t);
    transpose_in<<<dim3(1024, 4), dim3(32, 32)>>>(x, xt);

    // 1) QKV: [S,384] = xt * qkv_w^T
    gemm_mma<false,false><<<dim3(256, 3), 128, SMEM>>>(
        xt, qkv_w, qkv, qkv_b, 128, 384, nullptr, nullptr, nullptr);

    // 2) neighborhood attention
    attn3<<<dim3(HD, HD), 256>>>(qkv, sam, rpb);

    // 3) proj
    gemm_mma<false,false><<<dim3(256, 1), 128, SMEM>>>(
        sam, proj_w, y1, proj_b, 128, 128, nullptr, nullptr, nullptr);

    // 4) inorm stats of y1 + fold into fc1 weights
    stats_partial<<<256, 128>>>(y1, part);
    stats_final<<<1, 128>>>(part, m1, r1);
    w1fold<<<512, 128>>>(w1, b1, m1, r1, w1f, b1f);

    // 5) fc1 + relu (norm folded into w1f/b1f; reads raw y1)
    gemm_mma<true,false><<<dim3(256, 4), 128, SMEM>>>(
        y1, w1f, hid, b1f, 128, 512, nullptr, nullptr, nullptr);

    // 6) fc2 + normalized residual (epilogue applies (y1-m1)*r1)
    gemm_mma<false,true><<<dim3(256, 1), 128, SMEM>>>(
        hid, w2t, t2, b2, 512, 128, y1, m1, r1);

    // 7) inorm stats of t2
    stats_partial<<<256, 128>>>(t2, part);
    stats_final<<<1, 128>>>(part, m2, r2);

    // 8) skip = inorm(t2) + x; output = [down | skip]
    float* out  = (float*)d_out;
    float* down = out;
    float* skip = out + 524288;
    finalize2<<<dim3(1024, 4), dim3(32, 32)>>>(t2, x, m2, r2, skip);

    // 9) maxpool
    maxpool_kernel<<<2048, 256>>>(skip, down);
}

// round 6
// speedup vs baseline: 2.2073x; 1.0704x over previous
#include <cuda_runtime.h>
#include <stdint.h>
#include <math.h>

#define S_TOT 32768
#define HD 32

// ---------------- scratch (static device globals) ----------------
__device__ float g_xt  [S_TOT * 128];   // x transposed [S,C], tf32-rounded
__device__ float g_qkv [S_TOT * 384];
__device__ float g_sam [S_TOT * 128];   // tf32-rounded
__device__ float g_y1  [S_TOT * 128];   // tf32-rounded
__device__ float g_hid [S_TOT * 512];   // tf32-rounded
__device__ float g_t2  [S_TOT * 128];
__device__ float g_qw  [384 * 128];     // rounded qkv_w
__device__ float g_pw  [128 * 128];     // rounded proj_w
__device__ float g_w1f [512 * 128];     // folded+rounded fc1 weights
__device__ float g_w2t [128 * 512];     // rounded w2^T
__device__ float g_b1f [512];
__device__ float g_part[2 * S_TOT];
__device__ float g_stats[512];          // m1,r1,m2,r2

// ---------------- helpers ----------------
__device__ __forceinline__ uint32_t smem_u32(const void* p) {
    uint32_t a;
    asm("{ .reg .u64 t; cvta.to.shared.u64 t, %1; cvt.u32.u64 %0, t; }"
        : "=r"(a) : "l"(p));
    return a;
}
__device__ __forceinline__ void cp16(uint32_t s, const void* g) {
    asm volatile("cp.async.cg.shared.global [%0], [%1], 16;" :: "r"(s), "l"(g));
}
__device__ __forceinline__ void cp_commit() {
    asm volatile("cp.async.commit_group;" ::: "memory");
}
template<int N>
__device__ __forceinline__ void cp_wait() {
    asm volatile("cp.async.wait_group %0;" :: "n"(N) : "memory");
}
__device__ __forceinline__ float rtf32(float f) {
    uint32_t u;
    asm("cvt.rna.tf32.f32 %0, %1;" : "=r"(u) : "f"(f));
    return __uint_as_float(u);
}
__device__ __forceinline__ void ldsm4(uint32_t* r, uint32_t addr) {
    asm volatile("ldmatrix.sync.aligned.m8n8.x4.shared.b16 {%0,%1,%2,%3}, [%4];"
        : "=r"(r[0]), "=r"(r[1]), "=r"(r[2]), "=r"(r[3]) : "r"(addr));
}

// ============================================================
// tf32 mma.sync GEMM: Y[s0..+128, n0..+128) = A[S,Kd] * B[N,Kd]^T
// A, B MUST be tf32-pre-rounded. 128 threads, 4 warps (2Mx2N),
// warp tile 64x64, K-chunk 32, 3-stage cp.async, ldmatrix frags.
// ============================================================
#define KSTR 36
#define TILE_F (128 * KSTR)          // 18432 B per tile

template<bool RELU, bool RESID, bool ROUND>
__global__ void __launch_bounds__(128)
gemm_mma(const float* __restrict__ A, const float* __restrict__ B,
         float* __restrict__ Y, const float* __restrict__ bias,
         int Kd, int Nout, const float* __restrict__ resid,
         const float* __restrict__ mr, const float* __restrict__ rr)
{
    extern __shared__ float dsm[];

    const int tid = threadIdx.x;
    const int wid = tid >> 5;
    const int lane = tid & 31;
    const int wm = wid & 1;
    const int wn = wid >> 1;
    const int rq = lane >> 2;
    const int cq = lane & 3;
    const int s0 = blockIdx.x * 128;
    const int n0 = blockIdx.y * 128;

    const int nch = Kd >> 5;

    // ldmatrix per-lane offsets (bytes, relative to tile base)
    const uint32_t aOff = (uint32_t)(((wm * 64 + (lane & 7) + ((lane >> 3) & 1) * 8) * KSTR
                                     + ((lane >> 4) & 1) * 4) * 4);
    const uint32_t bOff = (uint32_t)(((wn * 64 + (lane & 7) + ((lane >> 4) & 1) * 8) * KSTR
                                     + ((lane >> 3) & 1) * 4) * 4);

    float acc[4][8][4];
#pragma unroll
    for (int mi = 0; mi < 4; mi++)
#pragma unroll
        for (int ni = 0; ni < 8; ni++)
#pragma unroll
            for (int r = 0; r < 4; r++) acc[mi][ni][r] = 0.f;

    auto load_chunk = [&](int ci, int buf) {
        const int kc = ci << 5;
        float* sA = dsm + buf * 2 * TILE_F;
        float* sB = sA + TILE_F;
        uint32_t aBase = smem_u32(sA);
        uint32_t bBase = smem_u32(sB);
#pragma unroll
        for (int j = 0; j < 8; j++) {
            int idx = tid + j * 128;
            int row = idx >> 3, seg = idx & 7;
            cp16(aBase + (row * KSTR + seg * 4) * 4,
                 &A[(size_t)(s0 + row) * Kd + kc + seg * 4]);
            cp16(bBase + (row * KSTR + seg * 4) * 4,
                 &B[(size_t)(n0 + row) * Kd + kc + seg * 4]);
        }
        cp_commit();
    };

    load_chunk(0, 0);
    load_chunk(1, 1);

    for (int ci = 0; ci < nch; ci++) {
        if (ci + 2 < nch)      { load_chunk(ci + 2, (ci + 2) % 3); cp_wait<2>(); }
        else if (ci + 1 < nch) { cp_wait<1>(); }
        else                   { cp_wait<0>(); }
        __syncthreads();

        const uint32_t sbase = smem_u32(dsm + (ci % 3) * 2 * TILE_F);
        const uint32_t aBase = sbase + aOff;
        const uint32_t bBase = sbase + (uint32_t)(TILE_F * 4) + bOff;

#pragma unroll
        for (int ks = 0; ks < 4; ks++) {
            uint32_t a[4][4], b[8][2];
#pragma unroll
            for (int mi = 0; mi < 4; mi++)
                ldsm4(a[mi], aBase + (uint32_t)((mi * 16 * KSTR + ks * 8) * 4));
#pragma unroll
            for (int nip = 0; nip < 4; nip++) {
                uint32_t r[4];
                ldsm4(r, bBase + (uint32_t)((nip * 16 * KSTR + ks * 8) * 4));
                b[2 * nip][0] = r[0]; b[2 * nip][1] = r[1];
                b[2 * nip + 1][0] = r[2]; b[2 * nip + 1][1] = r[3];
            }
#pragma unroll
            for (int mi = 0; mi < 4; mi++)
#pragma unroll
                for (int ni = 0; ni < 8; ni++) {
                    asm volatile(
                        "mma.sync.aligned.m16n8k8.row.col.f32.tf32.tf32.f32 "
                        "{%0,%1,%2,%3}, {%4,%5,%6,%7}, {%8,%9}, {%0,%1,%2,%3};"
                        : "+f"(acc[mi][ni][0]), "+f"(acc[mi][ni][1]),
                          "+f"(acc[mi][ni][2]), "+f"(acc[mi][ni][3])
                        : "r"(a[mi][0]), "r"(a[mi][1]), "r"(a[mi][2]), "r"(a[mi][3]),
                          "r"(b[ni][0]), "r"(b[ni][1]));
                }
        }
        __syncthreads();
    }

    // ---- epilogue ----
#pragma unroll
    for (int ni = 0; ni < 8; ni++) {
        const int col = n0 + wn * 64 + ni * 8 + cq * 2;
        const float b0 = bias[col], b1 = bias[col + 1];
        float m0 = 0.f, m1 = 0.f, r0 = 0.f, r1 = 0.f;
        if (RESID) { m0 = mr[col]; m1 = mr[col + 1]; r0 = rr[col]; r1 = rr[col + 1]; }
#pragma unroll
        for (int mi = 0; mi < 4; mi++) {
            const int row0 = s0 + wm * 64 + mi * 16 + rq;
#pragma unroll
            for (int half = 0; half < 2; half++) {
                const int row = row0 + half * 8;
                float v0 = acc[mi][ni][half * 2 + 0] + b0;
                float v1 = acc[mi][ni][half * 2 + 1] + b1;
                if (RELU) { v0 = fmaxf(v0, 0.f); v1 = fmaxf(v1, 0.f); }
                if (RESID) {
                    const float* rp = resid + (size_t)row * 128 + col;
                    v0 += (rp[0] - m0) * r0;
                    v1 += (rp[1] - m1) * r1;
                }
                if (ROUND) { v0 = rtf32(v0); v1 = rtf32(v1); }
                float2 o; o.x = v0; o.y = v1;
                *(float2*)&Y[(size_t)row * Nout + col] = o;
            }
        }
    }
}

// ============================================================
// Neighborhood attention (conflict-free slab); sam written tf32-rounded
// ============================================================
#define SLAB_STR 132

__global__ void __launch_bounds__(256)
attn3(const float* __restrict__ qkv, float* __restrict__ sam,
      const float* __restrict__ rpb)
{
    __shared__ __align__(16) float slab[32 * SLAB_STR];
    __shared__ float srpb[1000];

    const int h = blockIdx.y, w = blockIdx.x;
    const int tid = threadIdx.x;
    const int g = tid >> 5;
    const int z = tid & 31;

    for (int i = tid; i < 1000; i += 256) srpb[i] = rpb[i];

    const int c4 = tid & 31;
    auto fill = [&](int nh, int nw, int off) {
        const float* src = qkv + ((size_t)((nh * HD + nw) * HD)) * 384 + off;
#pragma unroll
        for (int i = 0; i < 4; i++) {
            const int idx = tid + i * 256;
            const int zz = idx >> 5;
            float4 v = *(const float4*)(src + (size_t)zz * 384 + c4 * 4);
            *(float4*)&slab[zz * SLAB_STR + c4 * 4] = v;
        }
    };

    fill(h, w, 0);
    __syncthreads();
    float qv[16];
#pragma unroll
    for (int j = 0; j < 4; j++) {
        float4 t = *(const float4*)&slab[z * SLAB_STR + g * 16 + j * 4];
        qv[j*4+0] = t.x; qv[j*4+1] = t.y; qv[j*4+2] = t.z; qv[j*4+3] = t.w;
    }

    const int sh = min(max(h - 1, 0), HD - 3);
    const int sw = min(max(w - 1, 0), HD - 3);
    const int sz = min(max(z - 1, 0), HD - 3);

    float logits[27];
#pragma unroll
    for (int jh = 0; jh < 3; jh++)
#pragma unroll
    for (int jw = 0; jw < 3; jw++) {
        const int nh = sh + jh, nw = sw + jw;
        __syncthreads();
        fill(nh, nw, 128);
        __syncthreads();
        const int rh = nh - h + 2, rw = nw - w + 2;
#pragma unroll
        for (int jz = 0; jz < 3; jz++) {
            const int nz = sz + jz;
            float dot = 0.f;
#pragma unroll
            for (int j = 0; j < 4; j++) {
                float4 kk = *(const float4*)&slab[nz * SLAB_STR + g * 16 + j * 4];
                dot += qv[j*4+0] * kk.x + qv[j*4+1] * kk.y
                     + qv[j*4+2] * kk.z + qv[j*4+3] * kk.w;
            }
            logits[(jh * 3 + jw) * 3 + jz] =
                dot * 0.25f + srpb[g * 125 + (rh * 5 + rw) * 5 + (nz - z + 2)];
        }
    }

    float mx = logits[0];
#pragma unroll
    for (int j = 1; j < 27; j++) mx = fmaxf(mx, logits[j]);
    float sum = 0.f;
#pragma unroll
    for (int j = 0; j < 27; j++) { logits[j] = __expf(logits[j] - mx); sum += logits[j]; }
    const float inv = 1.f / sum;

    float acc[16];
#pragma unroll
    for (int d = 0; d < 16; d++) acc[d] = 0.f;

#pragma unroll
    for (int jh = 0; jh < 3; jh++)
#pragma unroll
    for (int jw = 0; jw < 3; jw++) {
        const int nh = sh + jh, nw = sw + jw;
        __syncthreads();
        fill(nh, nw, 256);
        __syncthreads();
#pragma unroll
        for (int jz = 0; jz < 3; jz++) {
            const int nz = sz + jz;
            const float p = logits[(jh * 3 + jw) * 3 + jz] * inv;
#pragma unroll
            for (int j = 0; j < 4; j++) {
                float4 vv = *(const float4*)&slab[nz * SLAB_STR + g * 16 + j * 4];
                acc[j*4+0] += p * vv.x; acc[j*4+1] += p * vv.y;
                acc[j*4+2] += p * vv.z; acc[j*4+3] += p * vv.w;
            }
        }
    }

    __syncthreads();
#pragma unroll
    for (int j = 0; j < 4; j++) {
        float4 t;
        t.x = rtf32(acc[j*4+0]); t.y = rtf32(acc[j*4+1]);
        t.z = rtf32(acc[j*4+2]); t.w = rtf32(acc[j*4+3]);
        *(float4*)&slab[z * SLAB_STR + g * 16 + j * 4] = t;
    }
    __syncthreads();
    {
        float* dst = sam + ((size_t)((h * HD + w) * HD)) * 128;
#pragma unroll
        for (int i = 0; i < 4; i++) {
            const int idx = tid + i * 256;
            const int zz = idx >> 5;
            float4 v = *(const float4*)&slab[zz * SLAB_STR + c4 * 4];
            *(float4*)&dst[(size_t)zz * 128 + c4 * 4] = v;
        }
    }
}

// ---------------- misc kernels ----------------
// rounded weight copies: qkv_w (49152), proj_w (16384), w2t (65536)
__global__ void __launch_bounds__(256)
wprep(const float* __restrict__ qkv_w, const float* __restrict__ proj_w,
      const float* __restrict__ w2,
      float* __restrict__ qw, float* __restrict__ pw, float* __restrict__ w2t)
{
    int i = blockIdx.x * 256 + threadIdx.x;   // 65536
    if (i < 49152) qw[i] = rtf32(qkv_w[i]);
    if (i < 16384) pw[i] = rtf32(proj_w[i]);
    int f = i >> 7, c = i & 127;
    w2t[c * 512 + f] = rtf32(w2[i]);
}

__global__ void __launch_bounds__(128)
w1fold(const float* __restrict__ w1, const float* __restrict__ b1,
       const float* __restrict__ m1, const float* __restrict__ r1,
       float* __restrict__ w1f, float* __restrict__ b1f)
{
    const int f = blockIdx.x, c = threadIdx.x;
    float wv = w1[c * 512 + f] * r1[c];
    w1f[f * 128 + c] = rtf32(wv);
    __shared__ float sh[128];
    sh[c] = wv * m1[c];
    __syncthreads();
    for (int o = 64; o > 0; o >>= 1) {
        if (c < o) sh[c] += sh[c + o];
        __syncthreads();
    }
    if (c == 0) b1f[f] = b1[f] - sh[0];
}

__global__ void __launch_bounds__(1024)
transpose_in(const float* __restrict__ x, float* __restrict__ xt)
{
    __shared__ float t[32][33];
    const int s0 = blockIdx.x * 32, c0 = blockIdx.y * 32;
    const int tx = threadIdx.x, ty = threadIdx.y;
    t[ty][tx] = x[(size_t)(c0 + ty) * S_TOT + s0 + tx];
    __syncthreads();
    xt[(size_t)(s0 + ty) * 128 + c0 + tx] = rtf32(t[tx][ty]);
}

__global__ void __launch_bounds__(128)
stats_partial(const float* __restrict__ Y, float* __restrict__ part)
{
    const int c = threadIdx.x, b = blockIdx.x;
    float s = 0.f, s2 = 0.f;
    const float* p = Y + (size_t)b * 128 * 128;
    for (int r = 0; r < 128; r++) {
        float v = p[r * 128 + c];
        s += v; s2 += v * v;
    }
    part[b * 128 + c] = s;
    part[S_TOT + b * 128 + c] = s2;
}

__global__ void __launch_bounds__(128)
stats_final(const float* __restrict__ part, float* __restrict__ mean,
            float* __restrict__ rstd)
{
    const int c = threadIdx.x;
    float s = 0.f, s2 = 0.f;
    for (int b = 0; b < 256; b++) {
        s  += part[b * 128 + c];
        s2 += part[S_TOT + b * 128 + c];
    }
    const float m = s * (1.f / S_TOT);
    mean[c] = m;
    rstd[c] = rsqrtf(s2 * (1.f / S_TOT) - m * m + 1e-5f);
}

__global__ void __launch_bounds__(1024)
finalize2(const float* __restrict__ t2, const float* __restrict__ x,
          const float* __restrict__ m2, const float* __restrict__ r2,
          float* __restrict__ skip)
{
    __shared__ float t[32][33];
    const int s0 = blockIdx.x * 32, c0 = blockIdx.y * 32;
    const int tx = threadIdx.x, ty = threadIdx.y;
    t[ty][tx] = t2[(size_t)(s0 + ty) * 128 + c0 + tx];
    __syncthreads();
    const int c = c0 + ty, s = s0 + tx;
    skip[(size_t)c * S_TOT + s] = (t[tx][ty] - m2[c]) * r2[c] + x[(size_t)c * S_TOT + s];
}

__global__ void __launch_bounds__(256)
maxpool_kernel(const float* __restrict__ skip, float* __restrict__ down)
{
    int idx = blockIdx.x * 256 + threadIdx.x;
    int oz = idx & 15, ow = (idx >> 4) & 15, oh = (idx >> 8) & 15, c = idx >> 12;
    const float* p = skip + (((size_t)c * HD + oh * 2) * HD + ow * 2) * HD + oz * 2;
    float m = p[0];
    m = fmaxf(m, p[1]);
    m = fmaxf(m, p[HD]);           m = fmaxf(m, p[HD + 1]);
    m = fmaxf(m, p[HD * HD]);      m = fmaxf(m, p[HD * HD + 1]);
    m = fmaxf(m, p[HD * HD + HD]); m = fmaxf(m, p[HD * HD + HD + 1]);
    down[idx] = m;
}

// ============================================================
extern "C" void kernel_launch(void* const* d_in, const int* in_sizes, int n_in,
                              void* d_out, int out_size)
{
    const float* x      = (const float*)d_in[0];
    const float* qkv_w  = (const float*)d_in[1];
    const float* qkv_b  = (const float*)d_in[2];
    const float* proj_w = (const float*)d_in[3];
    const float* proj_b = (const float*)d_in[4];
    const float* rpb    = (const float*)d_in[5];
    const float* w1     = (const float*)d_in[6];
    const float* b1     = (const float*)d_in[7];
    const float* w2     = (const float*)d_in[8];
    const float* b2     = (const float*)d_in[9];

    float *xt, *qkv, *sam, *y1, *hid, *t2, *qw, *pw, *w1f, *w2t, *b1f, *part, *st;
    cudaGetSymbolAddress((void**)&xt,  g_xt);
    cudaGetSymbolAddress((void**)&qkv, g_qkv);
    cudaGetSymbolAddress((void**)&sam, g_sam);
    cudaGetSymbolAddress((void**)&y1,  g_y1);
    cudaGetSymbolAddress((void**)&hid, g_hid);
    cudaGetSymbolAddress((void**)&t2,  g_t2);
    cudaGetSymbolAddress((void**)&qw,  g_qw);
    cudaGetSymbolAddress((void**)&pw,  g_pw);
    cudaGetSymbolAddress((void**)&w1f, g_w1f);
    cudaGetSymbolAddress((void**)&w2t, g_w2t);
    cudaGetSymbolAddress((void**)&b1f, g_b1f);
    cudaGetSymbolAddress((void**)&part,g_part);
    cudaGetSymbolAddress((void**)&st,  g_stats);
    float *m1 = st, *r1 = st + 128, *m2 = st + 256, *r2 = st + 384;

    const int SMEM = 3 * 2 * TILE_F * sizeof(float);   // 110592 B
    cudaFuncSetAttribute(gemm_mma<false,false,false>,
                         cudaFuncAttributeMaxDynamicSharedMemorySize, SMEM);
    cudaFuncSetAttribute(gemm_mma<false,false,true>,
                         cudaFuncAttributeMaxDynamicSharedMemorySize, SMEM);
    cudaFuncSetAttribute(gemm_mma<true,false,true>,
                         cudaFuncAttributeMaxDynamicSharedMemorySize, SMEM);
    cudaFuncSetAttribute(gemm_mma<false,true,false>,
                         cudaFuncAttributeMaxDynamicSharedMemorySize, SMEM);

    // prep: rounded weights + input transpose (rounded)
    wprep<<<256, 256>>>(qkv_w, proj_w, w2, qw, pw, w2t);
    transpose_in<<<dim3(1024, 4), dim3(32, 32)>>>(x, xt);

    // 1) QKV: [S,384] = xt * qw^T  (output full fp32 — feeds attention)
    gemm_mma<false,false,false><<<dim3(256, 3), 128, SMEM>>>(
        xt, qw, qkv, qkv_b, 128, 384, nullptr, nullptr, nullptr);

    // 2) neighborhood attention (sam written tf32-rounded)
    attn3<<<dim3(HD, HD), 256>>>(qkv, sam, rpb);

    // 3) proj: y1 (rounded)
    gemm_mma<false,false,true><<<dim3(256, 1), 128, SMEM>>>(
        sam, pw, y1, proj_b, 128, 128, nullptr, nullptr, nullptr);

    // 4) inorm stats of y1 + fold into fc1 weights
    stats_partial<<<256, 128>>>(y1, part);
    stats_final<<<1, 128>>>(part, m1, r1);
    w1fold<<<512, 128>>>(w1, b1, m1, r1, w1f, b1f);

    // 5) fc1 + relu -> hid (rounded)
    gemm_mma<true,false,true><<<dim3(256, 4), 128, SMEM>>>(
        y1, w1f, hid, b1f, 128, 512, nullptr, nullptr, nullptr);

    // 6) fc2 + normalized residual -> t2 (full fp32)
    gemm_mma<false,true,false><<<dim3(256, 1), 128, SMEM>>>(
        hid, w2t, t2, b2, 512, 128, y1, m1, r1);

    // 7) inorm stats of t2
    stats_partial<<<256, 128>>>(t2, part);
    stats_final<<<1, 128>>>(part, m2, r2);

    // 8) skip = inorm(t2) + x; output = [down | skip]
    float* out  = (float*)d_out;
    float* down = out;
    float* skip = out + 524288;
    finalize2<<<dim3(1024, 4), dim3(32, 32)>>>(t2, x, m2, r2, skip);

    // 9) maxpool
    maxpool_kernel<<<2048, 256>>>(skip, down);
}